// round 13
// baseline (speedup 1.0000x reference)
#include <cuda_runtime.h>
#include <math.h>
#include <stdint.h>

#define DIMC 384
#define B_   8
#define HH   56
#define WW   56
#define T1   3136
#define H2   28
#define W2   28
#define T2   784
#define NHEADS 6
#define HD   64
#define EPSBN 1e-5f
#define ATT_SCALE 0.05103103630798288f   /* 384^-0.5 (full dim, per reference) */
#define LOG2E 1.4426950408889634f
#define WN (DIMC * DIMC)

// ---------------- scratch ---------------------------------------------------
__device__ float g_qf[B_ * T1 * DIMC];
__device__ float g_kf[B_ * T2 * DIMC];
__device__ float g_vf[B_ * T2 * DIMC];
__device__ float g_qp[B_ * T1 * DIMC];
__device__ float g_kp[B_ * T2 * DIMC];
__device__ float g_vp[B_ * T2 * DIMC];
__device__ float g_ob[B_ * T1 * DIMC];
__device__ float g_wr[4 * WN];          // tf32-rounded, sigma-permuted weights

// ---------------- helpers ---------------------------------------------------
// sigma: within each 16-group, original index t+4u (t,u in 0..3) stored at 4t+u.
// Makes fragment k-positions {t, t+4, t+8, t+12} contiguous -> LDS.128 frags.
__device__ __forceinline__ int sigma(int c) {
    int lo = c & 15;
    return (c & ~15) | (((lo & 3) << 2) | (lo >> 2));
}

__device__ __forceinline__ float tf32r(float x) {
    uint32_t u;
    asm("cvt.rna.tf32.f32 %0, %1;" : "=r"(u) : "f"(x));
    return __uint_as_float(u);
}

__device__ __forceinline__ void mma8(float* d, const uint32_t* a, uint32_t b0, uint32_t b1) {
    asm volatile(
        "mma.sync.aligned.m16n8k8.row.col.f32.tf32.tf32.f32 "
        "{%0,%1,%2,%3}, {%4,%5,%6,%7}, {%8,%9}, {%0,%1,%2,%3};\n"
        : "+f"(d[0]), "+f"(d[1]), "+f"(d[2]), "+f"(d[3])
        : "r"(a[0]), "r"(a[1]), "r"(a[2]), "r"(a[3]), "r"(b0), "r"(b1));
}

__device__ __forceinline__ void cpa16(uint32_t dst, const void* src) {
    asm volatile("cp.async.cg.shared.global [%0], [%1], 16;" :: "r"(dst), "l"(src));
}
__device__ __forceinline__ void cpa16z(uint32_t dst, const void* src, int sz) {
    asm volatile("cp.async.cg.shared.global [%0], [%1], 16, %2;" :: "r"(dst), "l"(src), "r"(sz));
}
__device__ __forceinline__ void cpa_commit() {
    asm volatile("cp.async.commit_group;");
}
__device__ __forceinline__ uint32_t smem_u32(const void* p) {
    return (uint32_t)__cvta_generic_to_shared(p);
}

// ---------------- prep: round + sigma-permute weights ------------------------
// Columns (k-dim) sigma-permuted for ALL matrices (matches sigma'd conv/ob
// activations). Rows (output features) sigma-permuted for wq,wk only (gives
// float4 Q/K fragment loads in attention).
__global__ __launch_bounds__(256) void round_w_k(
    const float* __restrict__ wq, const float* __restrict__ wk,
    const float* __restrict__ wv, const float* __restrict__ wl)
{
    int i = blockIdx.x * 256 + threadIdx.x;
    if (i < 4 * WN) {
        int m = i / WN, j = i - m * WN;
        int n = j / DIMC, col = j - n * DIMC;
        const float* s = (m == 0) ? wq : (m == 1) ? wk : (m == 2) ? wv : wl;
        int nd = (m < 2) ? sigma(n) : n;
        g_wr[m * WN + nd * DIMC + sigma(col)] = tf32r(s[j]);
    }
}

// ---------------- conv bodies (outputs written at sigma(c)) ------------------
__device__ __forceinline__ void dwconv_s1_body(
    int by,
    const float* __restrict__ x, const float* __restrict__ cw,
    const float* __restrict__ gs, const float* __restrict__ gb,
    const float* __restrict__ gm, const float* __restrict__ gv,
    float* __restrict__ out)
{
    const int b  = by / HH, y = by % HH;
    const int c  = threadIdx.x;

    const float w0 = cw[c*9+0], w1 = cw[c*9+1], w2 = cw[c*9+2];
    const float w3 = cw[c*9+3], w4 = cw[c*9+4], w5 = cw[c*9+5];
    const float w6 = cw[c*9+6], w7 = cw[c*9+7], w8 = cw[c*9+8];
    const float inv = rsqrtf(gv[c] + EPSBN);
    const float sc  = gs[c] * inv;
    const float bb  = gb[c] - gm[c] * sc;

    const float* base = x + (size_t)b * T1 * DIMC + c;
    const bool v0 = (y > 0), v2 = (y < HH - 1);
    const float* r0 = base + (size_t)(y - 1) * WW * DIMC;
    const float* r1 = base + (size_t)y * WW * DIMC;
    const float* r2 = base + (size_t)(y + 1) * WW * DIMC;
    float* op = out + ((size_t)b * T1 + (size_t)y * WW) * DIMC + sigma(c);

    float a0 = 0.f, a1 = 0.f, a2 = 0.f;
    float b0 = v0 ? r0[0] : 0.f;
    float b1 = r1[0];
    float b2 = v2 ? r2[0] : 0.f;
    float c0 = v0 ? r0[DIMC] : 0.f;
    float c1 = r1[DIMC];
    float c2 = v2 ? r2[DIMC] : 0.f;

    #pragma unroll 4
    for (int xw = 0; xw < WW; xw++) {
        float acc = a0*w0 + b0*w1 + c0*w2
                  + a1*w3 + b1*w4 + c1*w5
                  + a2*w6 + b2*w7 + c2*w8;
        op[(size_t)xw * DIMC] = tf32r(acc * sc + bb);
        a0 = b0; a1 = b1; a2 = b2;
        b0 = c0; b1 = c1; b2 = c2;
        if (xw + 2 < WW) {
            size_t off = (size_t)(xw + 2) * DIMC;
            c0 = v0 ? r0[off] : 0.f;
            c1 = r1[off];
            c2 = v2 ? r2[off] : 0.f;
        } else { c0 = c1 = c2 = 0.f; }
    }
}

__device__ __forceinline__ void dwconv_s2_body(
    int by,
    const float* __restrict__ x,
    const float* __restrict__ cwk, const float* __restrict__ ksc, const float* __restrict__ kbi,
    const float* __restrict__ kmu, const float* __restrict__ kva,
    const float* __restrict__ cwv, const float* __restrict__ vsc, const float* __restrict__ vbi,
    const float* __restrict__ vmu, const float* __restrict__ vva,
    float* __restrict__ outk, float* __restrict__ outv)
{
    const int b  = by / H2, oy = by % H2;
    const int c  = threadIdx.x;
    const int y  = 2 * oy;

    float wk[9], wv[9];
    #pragma unroll
    for (int i = 0; i < 9; i++) { wk[i] = cwk[c*9+i]; wv[i] = cwv[c*9+i]; }
    const float invk = rsqrtf(kva[c] + EPSBN);
    const float sck  = ksc[c] * invk;
    const float bbk  = kbi[c] - kmu[c] * sck;
    const float invv = rsqrtf(vva[c] + EPSBN);
    const float scv  = vsc[c] * invv;
    const float bbv  = vbi[c] - vmu[c] * scv;

    const float* base = x + (size_t)b * T1 * DIMC + c;
    const bool v0 = (y > 0), v2 = (y < HH - 1);
    const float* r0 = base + (size_t)(y - 1) * WW * DIMC;
    const float* r1 = base + (size_t)y * WW * DIMC;
    const float* r2 = base + (size_t)(y + 1) * WW * DIMC;
    float* opk = outk + ((size_t)b * T2 + (size_t)oy * W2) * DIMC + sigma(c);
    float* opv = outv + ((size_t)b * T2 + (size_t)oy * W2) * DIMC + sigma(c);

    float a0 = 0.f, a1 = 0.f, a2 = 0.f;
    float b0 = v0 ? r0[0] : 0.f, b1 = r1[0], b2 = v2 ? r2[0] : 0.f;
    float c0 = v0 ? r0[DIMC] : 0.f, c1 = r1[DIMC], c2 = v2 ? r2[DIMC] : 0.f;

    #pragma unroll 2
    for (int ox = 0; ox < W2; ox++) {
        float ak = a0*wk[0] + b0*wk[1] + c0*wk[2]
                 + a1*wk[3] + b1*wk[4] + c1*wk[5]
                 + a2*wk[6] + b2*wk[7] + c2*wk[8];
        float av = a0*wv[0] + b0*wv[1] + c0*wv[2]
                 + a1*wv[3] + b1*wv[4] + c1*wv[5]
                 + a2*wv[6] + b2*wv[7] + c2*wv[8];
        opk[(size_t)ox * DIMC] = tf32r(ak * sck + bbk);
        opv[(size_t)ox * DIMC] = tf32r(av * scv + bbv);
        if (ox + 1 < W2) {
            size_t o1 = (size_t)(2*ox + 2) * DIMC;
            size_t o2 = (size_t)(2*ox + 3) * DIMC;
            a0 = c0; a1 = c1; a2 = c2;
            b0 = v0 ? r0[o1] : 0.f; b1 = r1[o1]; b2 = v2 ? r2[o1] : 0.f;
            c0 = v0 ? r0[o2] : 0.f; c1 = r1[o2]; c2 = v2 ? r2[o2] : 0.f;
        }
    }
}

__global__ __launch_bounds__(DIMC) void conv_fused(
    const float* __restrict__ x,
    const float* __restrict__ cq,  const float* __restrict__ qsc, const float* __restrict__ qbi,
    const float* __restrict__ qmu, const float* __restrict__ qva,
    const float* __restrict__ cwk, const float* __restrict__ ksc, const float* __restrict__ kbi,
    const float* __restrict__ kmu, const float* __restrict__ kva,
    const float* __restrict__ cwv, const float* __restrict__ vsc, const float* __restrict__ vbi,
    const float* __restrict__ vmu, const float* __restrict__ vva,
    float* __restrict__ outq, float* __restrict__ outk, float* __restrict__ outv)
{
    const int bx = blockIdx.x;
    if (bx < B_ * HH) {
        dwconv_s1_body(bx, x, cq, qsc, qbi, qmu, qva, outq);
    } else {
        dwconv_s2_body(bx - B_ * HH, x, cwk, ksc, kbi, kmu, kva,
                       cwv, vsc, vbi, vmu, vva, outk, outv);
    }
}

// ---------------- tf32 GEMM body, float4 fragment loads ----------------------
// A and W are sigma-permuted along k. Smem rows 32 floats = 8 chunks; chunk j
// of row r stored at j^(4*(r&1)). A float4 at chunk (4*m2+t)^(4*(g&1)) yields
// the a0/a2 fragments for the kb-pair (2*m2, 2*m2+1); W likewise for b0/b1.
__device__ __forceinline__ void gemm_body(
    const float* __restrict__ A, const float* __restrict__ W,
    const float* __restrict__ bias, float* __restrict__ C,
    float oscale, int rnd, int row0, int col0)
{
    __shared__ __align__(16) float As[2][128 * 32];
    __shared__ __align__(16) float Ws[2][64 * 32];

    const int tid = threadIdx.x;
    const int w = tid >> 5, lane = tid & 31;
    const int g = lane >> 2, t = lane & 3;
    const int wm = (w & 1) * 64, wn = (w >> 1) * 32;
    const int g1 = 4 * (g & 1);

    float acc[4][4][4] = {};

    auto load_stage = [&](int s, int k0) {
        uint32_t abase = smem_u32(As[s]);
        uint32_t wbase = smem_u32(Ws[s]);
        #pragma unroll
        for (int p = 0; p < 8; p++) {
            int idx = tid + p * 128;
            int r = idx >> 3, j = idx & 7;
            cpa16(abase + r * 128 + ((j ^ (4 * (r & 1))) << 4),
                  A + (size_t)(row0 + r) * DIMC + k0 + j * 4);
        }
        #pragma unroll
        for (int p = 0; p < 4; p++) {
            int idx = tid + p * 128;
            int r = idx >> 3, j = idx & 7;
            cpa16(wbase + r * 128 + ((j ^ (4 * (r & 1))) << 4),
                  W + (size_t)(col0 + r) * DIMC + k0 + j * 4);
        }
        cpa_commit();
    };

    load_stage(0, 0);
    load_stage(1, 32);

    for (int ks = 0; ks < 12; ks++) {
        const int s = ks & 1;
        asm volatile("cp.async.wait_group 1;");
        __syncthreads();
        const float* Ac = As[s];
        const float* Wc = Ws[s];
        #pragma unroll
        for (int m2 = 0; m2 < 2; m2++) {
            const int ch = ((4 * m2 + t) ^ g1) << 2;
            float4 alo[4], ahi[4];
            #pragma unroll
            for (int mi = 0; mi < 4; mi++) {
                int r = wm + mi * 16 + g;
                alo[mi] = *(const float4*)&Ac[ r      * 32 + ch];
                ahi[mi] = *(const float4*)&Ac[(r + 8) * 32 + ch];
            }
            #pragma unroll
            for (int ni = 0; ni < 4; ni++) {
                int nr = wn + ni * 8 + g;
                float4 wf = *(const float4*)&Wc[nr * 32 + ch];
                uint32_t wb0 = __float_as_uint(wf.x), wb1 = __float_as_uint(wf.y);
                uint32_t wb2 = __float_as_uint(wf.z), wb3 = __float_as_uint(wf.w);
                #pragma unroll
                for (int mi = 0; mi < 4; mi++) {
                    uint32_t ae[4] = {__float_as_uint(alo[mi].x), __float_as_uint(ahi[mi].x),
                                      __float_as_uint(alo[mi].y), __float_as_uint(ahi[mi].y)};
                    uint32_t ao[4] = {__float_as_uint(alo[mi].z), __float_as_uint(ahi[mi].z),
                                      __float_as_uint(alo[mi].w), __float_as_uint(ahi[mi].w)};
                    mma8(acc[mi][ni], ae, wb0, wb1);
                    mma8(acc[mi][ni], ao, wb2, wb3);
                }
            }
        }
        __syncthreads();
        if (ks + 2 < 12) load_stage(s, (ks + 2) * 32);
        else cpa_commit();
    }

    #pragma unroll
    for (int mi = 0; mi < 4; mi++) {
        int r0 = row0 + wm + mi*16 + g;
        #pragma unroll
        for (int ni = 0; ni < 4; ni++) {
            int cc = col0 + wn + ni*8 + 2*t;
            float b0f = 0.f, b1f = 0.f;
            if (bias) { b0f = bias[cc]; b1f = bias[cc+1]; }
            float v0 = acc[mi][ni][0] * oscale + b0f;
            float v1 = acc[mi][ni][1] * oscale + b1f;
            float v2 = acc[mi][ni][2] * oscale + b0f;
            float v3 = acc[mi][ni][3] * oscale + b1f;
            if (rnd) { v0 = tf32r(v0); v1 = tf32r(v1); v2 = tf32r(v2); v3 = tf32r(v3); }
            *(float2*)&C[(size_t)r0 * DIMC + cc]       = make_float2(v0, v1);
            *(float2*)&C[(size_t)(r0 + 8) * DIMC + cc] = make_float2(v2, v3);
        }
    }
}

__global__ __launch_bounds__(128) void proj_fused(
    const float* __restrict__ qf, const float* __restrict__ kf,
    const float* __restrict__ vf,
    float* __restrict__ qp, float* __restrict__ kp, float* __restrict__ vp)
{
    const int z  = blockIdx.z;
    const int by = blockIdx.y;
    if (z > 0 && by >= (B_ * T2) / 128) return;

    const float* A = (z == 0) ? qf : (z == 1) ? kf : vf;
    const float* W = g_wr + z * WN;
    float*       C = (z == 0) ? qp : (z == 1) ? kp : vp;
    const float oscale = (z == 1) ? (ATT_SCALE * LOG2E) : 1.0f;

    gemm_body(A, W, nullptr, C, oscale, 1, by * 128, blockIdx.x * 64);
}

__global__ __launch_bounds__(128) void proj_last(
    const float* __restrict__ ob, const float* __restrict__ bias,
    float* __restrict__ out)
{
    gemm_body(ob, g_wr + 3 * WN, bias, out, 1.0f, 0,
              blockIdx.y * 128, blockIdx.x * 64);
}

// ---------------- tf32 flash attention, float4 K-frags, no-max softmax -------
// qp/kp columns are sigma-permuted (wq/wk rows) -> Q float4 gmem loads and
// K-tile LDS.128 fragment loads. K rows = 16 chunks, chunk j of row r stored
// at j^(4*(r&3)); load chunk (4m+t)^(4*(g&3)) (conflict-free per phase).
// V path and P shuffle permutation identical to round 12. Output columns
// written at sigma(dd) so proj_last's k-dim matches its sigma'd w_last.
__global__ __launch_bounds__(128) void attn_cp(
    const float* __restrict__ qp_, const float* __restrict__ kp_,
    const float* __restrict__ vp_, float* __restrict__ ob_)
{
    __shared__ __align__(16) float Ks[3][32 * 64];
    __shared__ __align__(16) float Vs[3][32 * 64];

    const int tid = threadIdx.x;
    const int w = tid >> 5, lane = tid & 31;
    const int g = lane >> 2, t = lane & 3;
    const int q0 = blockIdx.x * 128;
    const int h  = blockIdx.y;
    const int b  = blockIdx.z;

    const float* qp = qp_ + (size_t)b * T1 * DIMC + h * HD;
    const float* kp = kp_ + (size_t)b * T2 * DIMC + h * HD;
    const float* vp = vp_ + (size_t)b * T2 * DIMC + h * HD;

    const int kr = tid >> 4;
    const int kj = tid & 15;

    auto load_kv = [&](int buf, int kk0) {
        uint32_t kbase = smem_u32(Ks[buf]);
        uint32_t vbase = smem_u32(Vs[buf]);
        #pragma unroll
        for (int p = 0; p < 4; p++) {
            int r = kr + 8 * p;
            int key = kk0 + r;
            int ok  = (key < T2) ? 16 : 0;
            int kcl = (key < T2) ? key : (T2 - 1);
            cpa16z(kbase + r * 256 + ((kj ^ (4 * (r & 3))) << 4),
                   kp + (size_t)kcl * DIMC + kj * 4, ok);
            cpa16z(vbase + r * 256 + ((kj ^ (2 * (r & 3))) << 4),
                   vp + (size_t)kcl * DIMC + kj * 4, ok);
        }
        cpa_commit();
    };

    load_kv(0, 0);
    load_kv(1, 32);

    // Persistent Q fragments via float4 (sigma'd columns): qlo = row ra
    // (a0/a2 pairs for kb=2m,2m+1), qhi = row rb (a1/a3).
    const int rbase = q0 + w * 32;
    float4 qlo[2][4], qhi[2][4];
    #pragma unroll
    for (int s = 0; s < 2; s++) {
        int ra = rbase + s*16 + g;
        int rb = ra + 8;
        const float* pa = qp + (size_t)(ra < T1 ? ra : T1-1) * DIMC;
        const float* pb = qp + (size_t)(rb < T1 ? rb : T1-1) * DIMC;
        #pragma unroll
        for (int m = 0; m < 4; m++) {
            qlo[s][m] = *(const float4*)(pa + 16*m + 4*t);
            qhi[s][m] = *(const float4*)(pb + 16*m + 4*t);
        }
    }

    float O[2][8][4] = {};
    float lacc[4] = {0.f, 0.f, 0.f, 0.f};

    const int g3 = 4 * (g & 3);
    const int NTILE = (T2 + 31) / 32;
    for (int i = 0; i < NTILE; i++) {
        const int buf = i % 3;
        const int kk0 = i * 32;
        asm volatile("cp.async.wait_group 1;");
        __syncthreads();

        // ---- S = Q @ K'^T : float4 fragment loads, 4 mma per (m, nt) ----
        float S[2][4][4] = {};
        const float* Kc = Ks[buf];
        #pragma unroll
        for (int m = 0; m < 4; m++) {
            uint32_t a0e[4] = {__float_as_uint(qlo[0][m].x), __float_as_uint(qhi[0][m].x),
                               __float_as_uint(qlo[0][m].y), __float_as_uint(qhi[0][m].y)};
            uint32_t a0o[4] = {__float_as_uint(qlo[0][m].z), __float_as_uint(qhi[0][m].z),
                               __float_as_uint(qlo[0][m].w), __float_as_uint(qhi[0][m].w)};
            uint32_t a1e[4] = {__float_as_uint(qlo[1][m].x), __float_as_uint(qhi[1][m].x),
                               __float_as_uint(qlo[1][m].y), __float_as_uint(qhi[1][m].y)};
            uint32_t a1o[4] = {__float_as_uint(qlo[1][m].z), __float_as_uint(qhi[1][m].z),
                               __float_as_uint(qlo[1][m].w), __float_as_uint(qhi[1][m].w)};
            const int ch = ((4*m + t) ^ g3) << 2;
            #pragma unroll
            for (int nt = 0; nt < 4; nt++) {
                int n = nt*8 + g;
                float4 kf = *(const float4*)&Kc[n*64 + ch];
                uint32_t b0 = __float_as_uint(kf.x), b1 = __float_as_uint(kf.y);
                uint32_t b2 = __float_as_uint(kf.z), b3 = __float_as_uint(kf.w);
                mma8(S[0][nt], a0e, b0, b1);
                mma8(S[0][nt], a0o, b2, b3);
                mma8(S[1][nt], a1e, b0, b1);
                mma8(S[1][nt], a1o, b2, b3);
            }
        }

        // ---- mask padded keys (last tile only) ----
        if (kk0 + 32 > T2) {
            #pragma unroll
            for (int nt = 0; nt < 4; nt++) {
                int c0 = kk0 + nt*8 + 2*t;
                if (c0 >= T2)     { S[0][nt][0] = -1e30f; S[0][nt][2] = -1e30f;
                                    S[1][nt][0] = -1e30f; S[1][nt][2] = -1e30f; }
                if (c0 + 1 >= T2) { S[0][nt][1] = -1e30f; S[0][nt][3] = -1e30f;
                                    S[1][nt][1] = -1e30f; S[1][nt][3] = -1e30f; }
            }
        }

        // ---- P = exp2(S); accumulate partial l ----
        #pragma unroll
        for (int s = 0; s < 2; s++) {
            #pragma unroll
            for (int nt = 0; nt < 4; nt++) {
                float e0 = exp2f(S[s][nt][0]);
                float e1 = exp2f(S[s][nt][1]);
                float e2 = exp2f(S[s][nt][2]);
                float e3 = exp2f(S[s][nt][3]);
                S[s][nt][0] = e0; S[s][nt][1] = e1;
                S[s][nt][2] = e2; S[s][nt][3] = e3;
                lacc[s*2 + 0] += e0 + e1;
                lacc[s*2 + 1] += e2 + e3;
            }
        }

        // ---- O += P @ V (verified lane permutation; V path unchanged) ----
        const int L0 = (lane & 28) | (t >> 1);
        const int L2 = L0 + 2;
        const bool odd = (t & 1);
        const float* Vc = Vs[buf];
        #pragma unroll
        for (int kb = 0; kb < 4; kb++) {
            uint32_t pa[2][4];
            #pragma unroll
            for (int s = 0; s < 2; s++) {
                float e0 = __shfl_sync(0xffffffffu, S[s][kb][0], L0);
                float e1 = __shfl_sync(0xffffffffu, S[s][kb][1], L0);
                float f0 = __shfl_sync(0xffffffffu, S[s][kb][2], L0);
                float f1 = __shfl_sync(0xffffffffu, S[s][kb][3], L0);
                float h0 = __shfl_sync(0xffffffffu, S[s][kb][0], L2);
                float h1 = __shfl_sync(0xffffffffu, S[s][kb][1], L2);
                float i0 = __shfl_sync(0xffffffffu, S[s][kb][2], L2);
                float i1 = __shfl_sync(0xffffffffu, S[s][kb][3], L2);
                pa[s][0] = __float_as_uint(odd ? e1 : e0);
                pa[s][1] = __float_as_uint(odd ? f1 : f0);
                pa[s][2] = __float_as_uint(odd ? h1 : h0);
                pa[s][3] = __float_as_uint(odd ? i1 : i0);
            }
            const int vr0 = kb*8 + t;
            const int vr1 = kb*8 + t + 4;
            #pragma unroll
            for (int nt = 0; nt < 8; nt++) {
                int ch0 = nt*2 + (g >> 2);
                int cl  = g & 3;
                uint32_t b0 = __float_as_uint(Vc[vr0*64 + ((ch0 ^ (2*t)) << 2) + cl]);
                uint32_t b1 = __float_as_uint(Vc[vr1*64 + ((ch0 ^ (2*t)) << 2) + cl]);
                mma8(O[0][nt], pa[0], b0, b1);
                mma8(O[1][nt], pa[1], b0, b1);
            }
        }

        if (i + 2 < NTILE) load_kv((i + 2) % 3, (i + 2) * 32);
        else cpa_commit();
    }

    // ---- single deferred l reduction ----
    #pragma unroll
    for (int rc = 0; rc < 4; rc++) {
        lacc[rc] += __shfl_xor_sync(0xffffffffu, lacc[rc], 1);
        lacc[rc] += __shfl_xor_sync(0xffffffffu, lacc[rc], 2);
    }

    // ---- finalize: O / l, write at sigma(dd) (feeds sigma'd w_last) ----
    #pragma unroll
    for (int s = 0; s < 2; s++) {
        float inv0 = 1.f / lacc[s*2 + 0];
        float inv1 = 1.f / lacc[s*2 + 1];
        int r0 = rbase + s*16 + g;
        int r1 = r0 + 8;
        if (r0 < T1) {
            float* o0 = ob_ + ((size_t)b * T1 + r0) * DIMC + h * HD;
            #pragma unroll
            for (int nt = 0; nt < 8; nt++) {
                int dd = nt*8 + 2*t;
                o0[sigma(dd)]     = tf32r(O[s][nt][0] * inv0);
                o0[sigma(dd + 1)] = tf32r(O[s][nt][1] * inv0);
            }
        }
        if (r1 < T1) {
            float* o1 = ob_ + ((size_t)b * T1 + r1) * DIMC + h * HD;
            #pragma unroll
            for (int nt = 0; nt < 8; nt++) {
                int dd = nt*8 + 2*t;
                o1[sigma(dd)]     = tf32r(O[s][nt][2] * inv1);
                o1[sigma(dd + 1)] = tf32r(O[s][nt][3] * inv1);
            }
        }
    }
}

// ---------------- launch -----------------------------------------------------
extern "C" void kernel_launch(void* const* d_in, const int* in_sizes, int n_in,
                              void* d_out, int out_size)
{
    (void)in_sizes; (void)n_in; (void)out_size;
    const float* x      = (const float*)d_in[0];
    const float* conv_q = (const float*)d_in[3];
    const float* bnq_s  = (const float*)d_in[4];
    const float* bnq_b  = (const float*)d_in[5];
    const float* bnq_m  = (const float*)d_in[6];
    const float* bnq_v  = (const float*)d_in[7];
    const float* conv_k = (const float*)d_in[8];
    const float* bnk_s  = (const float*)d_in[9];
    const float* bnk_b  = (const float*)d_in[10];
    const float* bnk_m  = (const float*)d_in[11];
    const float* bnk_v  = (const float*)d_in[12];
    const float* conv_v = (const float*)d_in[13];
    const float* bnv_s  = (const float*)d_in[14];
    const float* bnv_b  = (const float*)d_in[15];
    const float* bnv_m  = (const float*)d_in[16];
    const float* bnv_v  = (const float*)d_in[17];
    const float* wq     = (const float*)d_in[18];
    const float* wk     = (const float*)d_in[19];
    const float* wv     = (const float*)d_in[20];
    const float* w_last = (const float*)d_in[21];
    const float* b_last = (const float*)d_in[22];
    float* out = (float*)d_out;

    float *qf, *kf, *vf, *qp, *kp, *vp, *ob;
    cudaGetSymbolAddress((void**)&qf, g_qf);
    cudaGetSymbolAddress((void**)&kf, g_kf);
    cudaGetSymbolAddress((void**)&vf, g_vf);
    cudaGetSymbolAddress((void**)&qp, g_qp);
    cudaGetSymbolAddress((void**)&kp, g_kp);
    cudaGetSymbolAddress((void**)&vp, g_vp);
    cudaGetSymbolAddress((void**)&ob, g_ob);

    // 1. weight prep (round + sigma permutations)
    round_w_k<<<(4 * WN + 255) / 256, 256>>>(wq, wk, wv, w_last);

    // 2. fused convs (sigma'd channel writes)
    conv_fused<<<B_ * HH + B_ * H2, DIMC>>>(
        x,
        conv_q, bnq_s, bnq_b, bnq_m, bnq_v,
        conv_k, bnk_s, bnk_b, bnk_m, bnk_v,
        conv_v, bnv_s, bnv_b, bnv_m, bnv_v,
        qf, kf, vf);

    // 3. fused q/k/v projections
    dim3 gproj(DIMC / 64, (B_ * T1) / 128, 3);   // (6, 196, 3)
    proj_fused<<<gproj, 128>>>(qf, kf, vf, qp, kp, vp);

    // 4. attention
    dim3 gattn((T1 + 127) / 128, NHEADS, B_);    // (25, 6, 8)
    attn_cp<<<gattn, 128>>>(qp, kp, vp, ob);

    // 5. final projection
    dim3 gbig(DIMC / 64, (B_ * T1) / 128);       // (6, 196)
    proj_last<<<gbig, 128>>>(ob, b_last, out);
}